// round 12
// baseline (speedup 1.0000x reference)
#include <cuda_runtime.h>
#include <stdint.h>
#include <math.h>

#define NN 20000
#define DD 256
#define HH 4
#define DHH 64
#define LL 2
#define EE 320000
#define KK 48
#define LN_EPS 1e-5f

// ---------------- scratch (static device globals; no allocation) -------------
__device__ float g_kv[LL][(size_t)NN * 2 * DD];   // per row: K[0:256) V[256:512)
__device__ float g_q[(size_t)NN * DD];
__device__ float g_x[(size_t)NN * DD];
__device__ float g_ao[(size_t)NN * DD];
__device__ float g_h[(size_t)NN * 2 * DD];
__device__ float g_t[(size_t)NN * DD];
__device__ int   g_counts[NN];
__device__ int   g_cnt[NN];
__device__ int   g_nbr[NN * KK];

// ---------------- neighbor build --------------------------------------------
__global__ void nbr_init_kernel() {
    int i = blockIdx.x * blockDim.x + threadIdx.x;
    if (i < NN) g_counts[i] = 0;
}

__global__ void nbr_scatter_kernel(const int* __restrict__ ei) {
    int e = blockIdx.x * blockDim.x + threadIdx.x;
    if (e >= EE) return;
    int s = ei[e];
    int t = ei[EE + e];
    int p = atomicAdd(&g_counts[t], 1);
    if (p < KK) g_nbr[t * KK + p] = s;
}

__global__ void nbr_fin_kernel() {
    int n = blockIdx.x * blockDim.x + threadIdx.x;
    if (n >= NN) return;
    int c = g_counts[n];
    if (c == 0) { g_nbr[n * KK] = n; c = 1; }
    g_cnt[n] = (c < KK) ? c : KK;
}

// ---------------- tf32 tensor-core GEMM, 3-stage cp.async, 1 sync/iter ------
// C[M,Nout] = A[M,Kd] @ B[Nout,Kd]^T + bias (+gelu)
// Both A and B fragments converted with cvt.rna at load (R9 numerics).

__device__ __forceinline__ unsigned f2tf(float x) {
    unsigned r;
    asm("cvt.rna.tf32.f32 %0, %1;" : "=r"(r) : "f"(x));
    return r;
}

#define SMS 36
#define TILE_F (128 * SMS)
#define STAGE_F (2 * TILE_F)
#define NSTAGE 3
#define GEMM_SMEM_BYTES (NSTAGE * STAGE_F * 4)   // 110592 B -> 2 CTAs/SM (216KB)

__device__ __forceinline__ uint32_t smem_u32(const void* p) {
    uint32_t a;
    asm("{ .reg .u64 t; cvta.to.shared.u64 t, %1; cvt.u32.u64 %0, t; }"
        : "=r"(a) : "l"(p));
    return a;
}

__global__ __launch_bounds__(256, 2) void gemm_tf32_kernel(
        const float* __restrict__ A,
        const float* __restrict__ B,
        const float* __restrict__ bias,
        float* __restrict__ C,
        int M, int Nout, int Kd, int act) {
    extern __shared__ float smem[];
    const uint32_t smem_base = smem_u32(smem);

    const int tid  = threadIdx.x;
    const int wid  = tid >> 5;
    const int lane = tid & 31;
    const int g    = lane >> 2;
    const int tg   = lane & 3;
    const int warp_m = wid & 3;
    const int warp_n = wid >> 2;
    const int m0 = blockIdx.y * 128;
    const int n0 = blockIdx.x * 128;

    const int row_ld = tid >> 3;
    const int col_ld = (tid & 7) * 4;

    const int nk = Kd >> 5;

    auto load_tile = [&](int kt, int s) {
        const int k0 = kt * 32;
        const uint32_t abase = smem_base + (uint32_t)s * STAGE_F * 4;
        const uint32_t bbase = abase + TILE_F * 4;
#pragma unroll
        for (int i = 0; i < 4; i++) {
            int row = row_ld + i * 32;
            int m = m0 + row;
            uint32_t adst = abase + (uint32_t)(row * SMS + col_ld) * 4;
            const float* asrc = A + (size_t)m * Kd + k0 + col_ld;
            int ab = (m < M) ? 16 : 0;
            asm volatile("cp.async.cg.shared.global [%0], [%1], 16, %2;"
                         :: "r"(adst), "l"(asrc), "r"(ab));
            uint32_t bdst = bbase + (uint32_t)(row * SMS + col_ld) * 4;
            const float* bsrc = B + (size_t)(n0 + row) * Kd + k0 + col_ld;
            asm volatile("cp.async.cg.shared.global [%0], [%1], 16, %2;"
                         :: "r"(bdst), "l"(bsrc), "r"(16));
        }
        asm volatile("cp.async.commit_group;");
    };

    // prologue: two tiles in flight
    load_tile(0, 0);
    if (nk > 1) load_tile(1, 1);

    float acc[2][8][4];
#pragma unroll
    for (int i = 0; i < 2; i++)
#pragma unroll
        for (int j = 0; j < 8; j++)
#pragma unroll
            for (int c = 0; c < 4; c++) acc[i][j][c] = 0.0f;

    int stage = 0;
    for (int kt = 0; kt < nk; kt++) {
        // ensure group kt complete (kt+1 may stay in flight)
        if (kt + 1 < nk) asm volatile("cp.async.wait_group 1;");
        else             asm volatile("cp.async.wait_group 0;");
        __syncthreads();   // also: all warps done reading stage(kt-1)

        // refill the stage last read at kt-1 with tile kt+2
        if (kt + 2 < nk) {
            int ns = stage + 2; if (ns >= NSTAGE) ns -= NSTAGE;
            load_tile(kt + 2, ns);
        }

        const float* As = smem + (size_t)stage * STAGE_F;
        const float* Bs = As + TILE_F;
#pragma unroll
        for (int ks = 0; ks < 4; ks++) {
            const int kk = ks * 8;
            unsigned a[2][4], b[8][2];
#pragma unroll
            for (int mt = 0; mt < 2; mt++) {
                int r = warp_m * 32 + mt * 16 + g;
                a[mt][0] = f2tf(As[r * SMS + kk + tg]);
                a[mt][1] = f2tf(As[(r + 8) * SMS + kk + tg]);
                a[mt][2] = f2tf(As[r * SMS + kk + tg + 4]);
                a[mt][3] = f2tf(As[(r + 8) * SMS + kk + tg + 4]);
            }
#pragma unroll
            for (int nt = 0; nt < 8; nt++) {
                int nb = warp_n * 64 + nt * 8 + g;
                b[nt][0] = f2tf(Bs[nb * SMS + kk + tg]);
                b[nt][1] = f2tf(Bs[nb * SMS + kk + tg + 4]);
            }
#pragma unroll
            for (int mt = 0; mt < 2; mt++)
#pragma unroll
                for (int nt = 0; nt < 8; nt++) {
                    asm volatile(
                        "mma.sync.aligned.m16n8k8.row.col.f32.tf32.tf32.f32 "
                        "{%0,%1,%2,%3}, {%4,%5,%6,%7}, {%8,%9}, {%0,%1,%2,%3};"
                        : "+f"(acc[mt][nt][0]), "+f"(acc[mt][nt][1]),
                          "+f"(acc[mt][nt][2]), "+f"(acc[mt][nt][3])
                        : "r"(a[mt][0]), "r"(a[mt][1]), "r"(a[mt][2]), "r"(a[mt][3]),
                          "r"(b[nt][0]), "r"(b[nt][1]));
                }
        }

        stage = stage + 1; if (stage >= NSTAGE) stage = 0;
    }

#pragma unroll
    for (int mt = 0; mt < 2; mt++) {
        int r0 = m0 + warp_m * 32 + mt * 16 + g;
        int r1 = r0 + 8;
#pragma unroll
        for (int nt = 0; nt < 8; nt++) {
            int cb = n0 + warp_n * 64 + nt * 8 + tg * 2;
            float bv0 = bias[cb], bv1 = bias[cb + 1];
            float v0 = acc[mt][nt][0] + bv0;
            float v1 = acc[mt][nt][1] + bv1;
            float v2 = acc[mt][nt][2] + bv0;
            float v3 = acc[mt][nt][3] + bv1;
            if (act) {
                v0 = 0.5f * v0 * (1.0f + erff(v0 * 0.70710678f));
                v1 = 0.5f * v1 * (1.0f + erff(v1 * 0.70710678f));
                v2 = 0.5f * v2 * (1.0f + erff(v2 * 0.70710678f));
                v3 = 0.5f * v3 * (1.0f + erff(v3 * 0.70710678f));
            }
            if (r0 < M) *(float2*)(C + (size_t)r0 * Nout + cb) = make_float2(v0, v1);
            if (r1 < M) *(float2*)(C + (size_t)r1 * Nout + cb) = make_float2(v2, v3);
        }
    }
}

// ---------------- attention: 2 nodes/block, one warp per (node,head) --------
__global__ __launch_bounds__(256) void attn_kernel(
        const float* __restrict__ q,
        const float* __restrict__ kv,
        float* __restrict__ ao) {
    const int local = threadIdx.x >> 7;
    const int n = blockIdx.x * 2 + local;
    const int warp = (threadIdx.x >> 5) & 3;
    const int lane = threadIdx.x & 31;

    __shared__ float s_sc[2][HH][KK];
    __shared__ int   s_nbr[2][KK];
    __shared__ int   s_cnt[2];

    if (n < NN) {
        const int t = threadIdx.x & 127;
        if (t == 0) s_cnt[local] = g_cnt[n];
        for (int j = t; j < KK; j += 128) s_nbr[local][j] = g_nbr[n * KK + j];
    }
    __syncthreads();
    if (n >= NN) return;
    const int cnt = s_cnt[local];

    const float2* q2 = (const float2*)(q + (size_t)n * DD + warp * DHH);
    float2 myq = q2[lane];

    for (int j = 0; j < cnt; j++) {
        const float2* k2 = (const float2*)(kv + (size_t)s_nbr[local][j] * (2 * DD) + warp * DHH);
        float2 kvv = k2[lane];
        float dot = myq.x * kvv.x + myq.y * kvv.y;
#pragma unroll
        for (int o = 16; o; o >>= 1) dot += __shfl_xor_sync(0xffffffffu, dot, o);
        if (lane == 0) s_sc[local][warp][j] = dot * 0.125f;
    }
    __syncwarp();

    float a0 = (lane < cnt) ? s_sc[local][warp][lane] : -1e30f;
    float a1 = (lane + 32 < cnt) ? s_sc[local][warp][lane + 32] : -1e30f;
    float mx = fmaxf(a0, a1);
#pragma unroll
    for (int o = 16; o; o >>= 1) mx = fmaxf(mx, __shfl_xor_sync(0xffffffffu, mx, o));
    float e0 = (lane < cnt) ? __expf(a0 - mx) : 0.0f;
    float e1 = (lane + 32 < cnt) ? __expf(a1 - mx) : 0.0f;
    float s = e0 + e1;
#pragma unroll
    for (int o = 16; o; o >>= 1) s += __shfl_xor_sync(0xffffffffu, s, o);
    float inv = 1.0f / s;
    s_sc[local][warp][lane] = e0 * inv;
    if (lane + 32 < KK) s_sc[local][warp][lane + 32] = e1 * inv;
    __syncwarp();

    float2 acc = {0.0f, 0.0f};
    for (int j = 0; j < cnt; j++) {
        float w = s_sc[local][warp][j];
        const float2* vp = (const float2*)(kv + (size_t)s_nbr[local][j] * (2 * DD) + DD + warp * DHH);
        float2 vv = vp[lane];
        acc.x += w * vv.x;
        acc.y += w * vv.y;
    }
    ((float2*)(ao + (size_t)n * DD + warp * DHH))[lane] = acc;
}

// ---------------- residual add + layernorm: 2 rows per 512-thread block -----
__global__ __launch_bounds__(512) void add_ln_kernel(
        const float* __restrict__ x,
        const float* __restrict__ y,
        const float* __restrict__ g,
        const float* __restrict__ b,
        float* __restrict__ out) {
    const int local = threadIdx.x >> 8;          // 0..1
    const int n = blockIdx.x * 2 + local;
    const int t = threadIdx.x & 255;
    if (n >= NN) return;
    size_t idx = (size_t)n * DD + t;
    float v = x[idx] + y[idx];

    float s = v, s2 = v * v;
#pragma unroll
    for (int o = 16; o; o >>= 1) {
        s  += __shfl_xor_sync(0xffffffffu, s,  o);
        s2 += __shfl_xor_sync(0xffffffffu, s2, o);
    }
    __shared__ float rs[2][8], rs2[2][8];
    if ((t & 31) == 0) { rs[local][t >> 5] = s; rs2[local][t >> 5] = s2; }
    __syncthreads();
    float S = 0.0f, S2 = 0.0f;
#pragma unroll
    for (int i = 0; i < 8; i++) { S += rs[local][i]; S2 += rs2[local][i]; }
    float mu  = S * (1.0f / DD);
    float var = S2 * (1.0f / DD) - mu * mu;
    out[idx] = (v - mu) * rsqrtf(var + LN_EPS) * g[t] + b[t];
}

// ---------------- launch -----------------------------------------------------
static inline void run_gemm(const float* A, const float* B, const float* bias,
                            float* C, int M, int Nout, int Kd, int act) {
    dim3 grid(Nout / 128, (M + 127) / 128);
    gemm_tf32_kernel<<<grid, 256, GEMM_SMEM_BYTES>>>(A, B, bias, C, M, Nout, Kd, act);
}

extern "C" void kernel_launch(void* const* d_in, const int* in_sizes, int n_in,
                              void* d_out, int out_size) {
    const float* expr    = (const float*)d_in[0];
    const float* spatial = (const float*)d_in[1];
    const float* ipw     = (const float*)d_in[2];
    const float* ipb     = (const float*)d_in[3];
    const float* opw     = (const float*)d_in[4];
    const float* opb     = (const float*)d_in[5];
    const float* w1      = (const float*)d_in[6];
    const float* b1      = (const float*)d_in[7];
    const float* w2      = (const float*)d_in[8];
    const float* b2      = (const float*)d_in[9];
    const float* ln1g    = (const float*)d_in[10];
    const float* ln1b    = (const float*)d_in[11];
    const float* ln2g    = (const float*)d_in[12];
    const float* ln2b    = (const float*)d_in[13];
    const int*   ei      = (const int*)d_in[14];
    float* out = (float*)d_out;

    static int smem_set = 0;
    if (!smem_set) {
        cudaFuncSetAttribute(gemm_tf32_kernel,
                             cudaFuncAttributeMaxDynamicSharedMemorySize,
                             GEMM_SMEM_BYTES);
        smem_set = 1;
    }

    float *kv, *q, *x, *ao, *h, *tmp;
    cudaGetSymbolAddress((void**)&kv,  g_kv);
    cudaGetSymbolAddress((void**)&q,   g_q);
    cudaGetSymbolAddress((void**)&x,   g_x);
    cudaGetSymbolAddress((void**)&ao,  g_ao);
    cudaGetSymbolAddress((void**)&h,   g_h);
    cudaGetSymbolAddress((void**)&tmp, g_t);

    nbr_init_kernel<<<(NN + 255) / 256, 256>>>();
    nbr_scatter_kernel<<<(EE + 255) / 256, 256>>>(ei);
    nbr_fin_kernel<<<(NN + 255) / 256, 256>>>();

    // fused K+V projection: rows [D, 3D) of in_proj are [Wk; Wv] (512 x 256)
    for (int l = 0; l < LL; l++) {
        const float* Wkv = ipw + ((size_t)l * 3 * DD + DD) * DD;
        const float* bkv = ipb + (size_t)l * 3 * DD + DD;
        run_gemm(spatial, Wkv, bkv, kv + (size_t)l * NN * 2 * DD, NN, 2 * DD, DD, 0);
    }

    for (int l = 0; l < LL; l++) {
        const float* xin = (l == 0) ? expr : x;
        const float* Wq = ipw + (size_t)l * 3 * DD * DD;
        const float* bq = ipb + (size_t)l * 3 * DD;

        run_gemm(xin, Wq, bq, q, NN, DD, DD, 0);

        attn_kernel<<<(NN + 1) / 2, 256>>>(q, kv + (size_t)l * NN * 2 * DD, ao);

        run_gemm(ao, opw + (size_t)l * DD * DD, opb + (size_t)l * DD,
                 tmp, NN, DD, DD, 0);

        add_ln_kernel<<<(NN + 1) / 2, 512>>>(xin, tmp, ln1g + (size_t)l * DD,
                                             ln1b + (size_t)l * DD, x);

        run_gemm(x, w1 + (size_t)l * 2 * DD * DD, b1 + (size_t)l * 2 * DD,
                 h, NN, 2 * DD, DD, 1);
        run_gemm(h, w2 + (size_t)l * DD * 2 * DD, b2 + (size_t)l * DD,
                 tmp, NN, DD, 2 * DD, 0);

        float* xo = (l == LL - 1) ? out : x;
        add_ln_kernel<<<(NN + 1) / 2, 512>>>(x, tmp, ln2g + (size_t)l * DD,
                                             ln2b + (size_t)l * DD, xo);
    }
}

// round 13
// speedup vs baseline: 1.1259x; 1.1259x over previous
#include <cuda_runtime.h>
#include <stdint.h>
#include <math.h>

#define NN 20000
#define DD 256
#define HH 4
#define DHH 64
#define LL 2
#define EE 320000
#define KK 48
#define LN_EPS 1e-5f

// ---------------- scratch (static device globals; no allocation) -------------
__device__ float g_kv[LL][(size_t)NN * 2 * DD];   // per row: K[0:256) V[256:512)
__device__ float g_q[(size_t)NN * DD];
__device__ float g_x[(size_t)NN * DD];
__device__ float g_ao[(size_t)NN * DD];
__device__ float g_h[(size_t)NN * 2 * DD];
__device__ float g_t[(size_t)NN * DD];
__device__ int   g_counts[NN];
__device__ int   g_cnt[NN];
__device__ int   g_nbr[NN * KK];

// ---------------- neighbor build --------------------------------------------
__global__ void nbr_init_kernel() {
    int i = blockIdx.x * blockDim.x + threadIdx.x;
    if (i < NN) g_counts[i] = 0;
}

__global__ void nbr_scatter_kernel(const int* __restrict__ ei) {
    int e = blockIdx.x * blockDim.x + threadIdx.x;
    if (e >= EE) return;
    int s = ei[e];
    int t = ei[EE + e];
    int p = atomicAdd(&g_counts[t], 1);
    if (p < KK) g_nbr[t * KK + p] = s;
}

__global__ void nbr_fin_kernel() {
    int n = blockIdx.x * blockDim.x + threadIdx.x;
    if (n >= NN) return;
    int c = g_counts[n];
    if (c == 0) { g_nbr[n * KK] = n; c = 1; }
    g_cnt[n] = (c < KK) ? c : KK;
}

// ---------------- tf32 tensor-core GEMM, 2-stage cp.async, 2 CTAs/SM ---------
// (identical to R9 best)

__device__ __forceinline__ unsigned f2tf(float x) {
    unsigned r;
    asm("cvt.rna.tf32.f32 %0, %1;" : "=r"(r) : "f"(x));
    return r;
}

#define SMS 36
#define TILE_F (128 * SMS)
#define STAGE_F (2 * TILE_F)
#define NSTAGE 2
#define GEMM_SMEM_BYTES (NSTAGE * STAGE_F * 4)   // 73728 B -> 2 CTAs/SM

__device__ __forceinline__ uint32_t smem_u32(const void* p) {
    uint32_t a;
    asm("{ .reg .u64 t; cvta.to.shared.u64 t, %1; cvt.u32.u64 %0, t; }"
        : "=r"(a) : "l"(p));
    return a;
}

__global__ __launch_bounds__(256, 2) void gemm_tf32_kernel(
        const float* __restrict__ A,
        const float* __restrict__ B,
        const float* __restrict__ bias,
        float* __restrict__ C,
        int M, int Nout, int Kd, int act) {
    extern __shared__ float smem[];
    const uint32_t smem_base = smem_u32(smem);

    const int tid  = threadIdx.x;
    const int wid  = tid >> 5;
    const int lane = tid & 31;
    const int g    = lane >> 2;
    const int tg   = lane & 3;
    const int warp_m = wid & 3;
    const int warp_n = wid >> 2;
    const int m0 = blockIdx.y * 128;
    const int n0 = blockIdx.x * 128;

    const int row_ld = tid >> 3;
    const int col_ld = (tid & 7) * 4;

    const int nk = Kd >> 5;

    auto load_tile = [&](int kt, int s) {
        const int k0 = kt * 32;
        const uint32_t abase = smem_base + (uint32_t)s * STAGE_F * 4;
        const uint32_t bbase = abase + TILE_F * 4;
#pragma unroll
        for (int i = 0; i < 4; i++) {
            int row = row_ld + i * 32;
            int m = m0 + row;
            uint32_t adst = abase + (uint32_t)(row * SMS + col_ld) * 4;
            const float* asrc = A + (size_t)m * Kd + k0 + col_ld;
            int ab = (m < M) ? 16 : 0;
            asm volatile("cp.async.cg.shared.global [%0], [%1], 16, %2;"
                         :: "r"(adst), "l"(asrc), "r"(ab));
            uint32_t bdst = bbase + (uint32_t)(row * SMS + col_ld) * 4;
            const float* bsrc = B + (size_t)(n0 + row) * Kd + k0 + col_ld;
            asm volatile("cp.async.cg.shared.global [%0], [%1], 16, %2;"
                         :: "r"(bdst), "l"(bsrc), "r"(16));
        }
        asm volatile("cp.async.commit_group;");
    };

    load_tile(0, 0);
    if (nk > 1) load_tile(1, 1);

    float acc[2][8][4];
#pragma unroll
    for (int i = 0; i < 2; i++)
#pragma unroll
        for (int j = 0; j < 8; j++)
#pragma unroll
            for (int c = 0; c < 4; c++) acc[i][j][c] = 0.0f;

    for (int kt = 0; kt < nk; kt++) {
        const int s = kt & 1;
        asm volatile("cp.async.wait_group 1;");
        __syncthreads();

        const float* As = smem + (size_t)s * STAGE_F;
        const float* Bs = As + TILE_F;
#pragma unroll
        for (int ks = 0; ks < 4; ks++) {
            const int kk = ks * 8;
            unsigned a[2][4], b[8][2];
#pragma unroll
            for (int mt = 0; mt < 2; mt++) {
                int r = warp_m * 32 + mt * 16 + g;
                a[mt][0] = f2tf(As[r * SMS + kk + tg]);
                a[mt][1] = f2tf(As[(r + 8) * SMS + kk + tg]);
                a[mt][2] = f2tf(As[r * SMS + kk + tg + 4]);
                a[mt][3] = f2tf(As[(r + 8) * SMS + kk + tg + 4]);
            }
#pragma unroll
            for (int nt = 0; nt < 8; nt++) {
                int nb = warp_n * 64 + nt * 8 + g;
                b[nt][0] = f2tf(Bs[nb * SMS + kk + tg]);
                b[nt][1] = f2tf(Bs[nb * SMS + kk + tg + 4]);
            }
#pragma unroll
            for (int mt = 0; mt < 2; mt++)
#pragma unroll
                for (int nt = 0; nt < 8; nt++) {
                    asm volatile(
                        "mma.sync.aligned.m16n8k8.row.col.f32.tf32.tf32.f32 "
                        "{%0,%1,%2,%3}, {%4,%5,%6,%7}, {%8,%9}, {%0,%1,%2,%3};"
                        : "+f"(acc[mt][nt][0]), "+f"(acc[mt][nt][1]),
                          "+f"(acc[mt][nt][2]), "+f"(acc[mt][nt][3])
                        : "r"(a[mt][0]), "r"(a[mt][1]), "r"(a[mt][2]), "r"(a[mt][3]),
                          "r"(b[nt][0]), "r"(b[nt][1]));
                }
        }
        __syncthreads();

        if (kt + 2 < nk) load_tile(kt + 2, s);
    }

#pragma unroll
    for (int mt = 0; mt < 2; mt++) {
        int r0 = m0 + warp_m * 32 + mt * 16 + g;
        int r1 = r0 + 8;
#pragma unroll
        for (int nt = 0; nt < 8; nt++) {
            int cb = n0 + warp_n * 64 + nt * 8 + tg * 2;
            float bv0 = bias[cb], bv1 = bias[cb + 1];
            float v0 = acc[mt][nt][0] + bv0;
            float v1 = acc[mt][nt][1] + bv1;
            float v2 = acc[mt][nt][2] + bv0;
            float v3 = acc[mt][nt][3] + bv1;
            if (act) {
                v0 = 0.5f * v0 * (1.0f + erff(v0 * 0.70710678f));
                v1 = 0.5f * v1 * (1.0f + erff(v1 * 0.70710678f));
                v2 = 0.5f * v2 * (1.0f + erff(v2 * 0.70710678f));
                v3 = 0.5f * v3 * (1.0f + erff(v3 * 0.70710678f));
            }
            if (r0 < M) *(float2*)(C + (size_t)r0 * Nout + cb) = make_float2(v0, v1);
            if (r1 < M) *(float2*)(C + (size_t)r1 * Nout + cb) = make_float2(v2, v3);
        }
    }
}

// ---------------- attention: 2 nodes/block, one warp per (node,head) --------
// Score phase: 4 neighbors per warp pass, 8-lane cooperative dots (3 shfl).
__global__ __launch_bounds__(256) void attn_kernel(
        const float* __restrict__ q,
        const float* __restrict__ kv,
        float* __restrict__ ao) {
    const int local = threadIdx.x >> 7;
    const int n = blockIdx.x * 2 + local;
    const int warp = (threadIdx.x >> 5) & 3;
    const int lane = threadIdx.x & 31;

    __shared__ float s_sc[2][HH][KK];
    __shared__ int   s_nbr[2][KK];
    __shared__ int   s_cnt[2];

    if (n < NN) {
        const int t = threadIdx.x & 127;
        if (t == 0) s_cnt[local] = g_cnt[n];
        for (int j = t; j < KK; j += 128) s_nbr[local][j] = g_nbr[n * KK + j];
    }
    __syncthreads();
    if (n >= NN) return;
    const int cnt = s_cnt[local];

    const int sub = lane >> 3;   // 0..3 : which of 4 neighbors this pass
    const int lr  = lane & 7;    // 0..7 : 8 floats each over DH=64

    const float4* qb = (const float4*)(q + (size_t)n * DD + warp * DHH + lr * 8);
    float4 q0 = qb[0], q1 = qb[1];

    // scores: 4 neighbors per pass, 8-lane dot + 3-shfl reduce
    for (int j0 = 0; j0 < cnt; j0 += 4) {
        int j = j0 + sub;
        float dot = 0.0f;
        if (j < cnt) {
            const float4* kp = (const float4*)(kv + (size_t)s_nbr[local][j] * (2 * DD) + warp * DHH + lr * 8);
            float4 k0 = kp[0], k1 = kp[1];
            dot = q0.x * k0.x + q0.y * k0.y + q0.z * k0.z + q0.w * k0.w
                + q1.x * k1.x + q1.y * k1.y + q1.z * k1.z + q1.w * k1.w;
        }
        dot += __shfl_xor_sync(0xffffffffu, dot, 1);
        dot += __shfl_xor_sync(0xffffffffu, dot, 2);
        dot += __shfl_xor_sync(0xffffffffu, dot, 4);
        if (lr == 0 && j < cnt) s_sc[local][warp][j] = dot * 0.125f;   // 1/sqrt(64)
    }
    __syncwarp();

    // softmax over [0, cnt)
    float a0 = (lane < cnt) ? s_sc[local][warp][lane] : -1e30f;
    float a1 = (lane + 32 < cnt) ? s_sc[local][warp][lane + 32] : -1e30f;
    float mx = fmaxf(a0, a1);
#pragma unroll
    for (int o = 16; o; o >>= 1) mx = fmaxf(mx, __shfl_xor_sync(0xffffffffu, mx, o));
    float e0 = (lane < cnt) ? __expf(a0 - mx) : 0.0f;
    float e1 = (lane + 32 < cnt) ? __expf(a1 - mx) : 0.0f;
    float s = e0 + e1;
#pragma unroll
    for (int o = 16; o; o >>= 1) s += __shfl_xor_sync(0xffffffffu, s, o);
    float inv = 1.0f / s;
    s_sc[local][warp][lane] = e0 * inv;
    if (lane + 32 < KK) s_sc[local][warp][lane + 32] = e1 * inv;
    __syncwarp();

    // weighted V sum (lane = feature pair)
    float2 acc = {0.0f, 0.0f};
    for (int j = 0; j < cnt; j++) {
        float w = s_sc[local][warp][j];
        const float2* vp = (const float2*)(kv + (size_t)s_nbr[local][j] * (2 * DD) + DD + warp * DHH);
        float2 vv = vp[lane];
        acc.x += w * vv.x;
        acc.y += w * vv.y;
    }
    ((float2*)(ao + (size_t)n * DD + warp * DHH))[lane] = acc;
}

// ---------------- residual add + layernorm -----------------------------------
__global__ void add_ln_kernel(const float* __restrict__ x,
                              const float* __restrict__ y,
                              const float* __restrict__ g,
                              const float* __restrict__ b,
                              float* __restrict__ out) {
    int n = blockIdx.x;
    int t = threadIdx.x;
    size_t idx = (size_t)n * DD + t;
    float v = x[idx] + y[idx];

    float s = v, s2 = v * v;
#pragma unroll
    for (int o = 16; o; o >>= 1) {
        s  += __shfl_xor_sync(0xffffffffu, s,  o);
        s2 += __shfl_xor_sync(0xffffffffu, s2, o);
    }
    __shared__ float rs[8], rs2[8];
    if ((t & 31) == 0) { rs[t >> 5] = s; rs2[t >> 5] = s2; }
    __syncthreads();
    float S = 0.0f, S2 = 0.0f;
#pragma unroll
    for (int i = 0; i < 8; i++) { S += rs[i]; S2 += rs2[i]; }
    float mu  = S * (1.0f / DD);
    float var = S2 * (1.0f / DD) - mu * mu;
    out[idx] = (v - mu) * rsqrtf(var + LN_EPS) * g[t] + b[t];
}

// ---------------- launch -----------------------------------------------------
static inline void run_gemm(const float* A, const float* B, const float* bias,
                            float* C, int M, int Nout, int Kd, int act) {
    dim3 grid(Nout / 128, (M + 127) / 128);
    gemm_tf32_kernel<<<grid, 256, GEMM_SMEM_BYTES>>>(A, B, bias, C, M, Nout, Kd, act);
}

extern "C" void kernel_launch(void* const* d_in, const int* in_sizes, int n_in,
                              void* d_out, int out_size) {
    const float* expr    = (const float*)d_in[0];
    const float* spatial = (const float*)d_in[1];
    const float* ipw     = (const float*)d_in[2];
    const float* ipb     = (const float*)d_in[3];
    const float* opw     = (const float*)d_in[4];
    const float* opb     = (const float*)d_in[5];
    const float* w1      = (const float*)d_in[6];
    const float* b1      = (const float*)d_in[7];
    const float* w2      = (const float*)d_in[8];
    const float* b2      = (const float*)d_in[9];
    const float* ln1g    = (const float*)d_in[10];
    const float* ln1b    = (const float*)d_in[11];
    const float* ln2g    = (const float*)d_in[12];
    const float* ln2b    = (const float*)d_in[13];
    const int*   ei      = (const int*)d_in[14];
    float* out = (float*)d_out;

    static int smem_set = 0;
    if (!smem_set) {
        cudaFuncSetAttribute(gemm_tf32_kernel,
                             cudaFuncAttributeMaxDynamicSharedMemorySize,
                             GEMM_SMEM_BYTES);
        smem_set = 1;
    }

    float *kv, *q, *x, *ao, *h, *tmp;
    cudaGetSymbolAddress((void**)&kv,  g_kv);
    cudaGetSymbolAddress((void**)&q,   g_q);
    cudaGetSymbolAddress((void**)&x,   g_x);
    cudaGetSymbolAddress((void**)&ao,  g_ao);
    cudaGetSymbolAddress((void**)&h,   g_h);
    cudaGetSymbolAddress((void**)&tmp, g_t);

    nbr_init_kernel<<<(NN + 255) / 256, 256>>>();
    nbr_scatter_kernel<<<(EE + 255) / 256, 256>>>(ei);
    nbr_fin_kernel<<<(NN + 255) / 256, 256>>>();

    // fused K+V projection: rows [D, 3D) of in_proj are [Wk; Wv] (512 x 256)
    for (int l = 0; l < LL; l++) {
        const float* Wkv = ipw + ((size_t)l * 3 * DD + DD) * DD;
        const float* bkv = ipb + (size_t)l * 3 * DD + DD;
        run_gemm(spatial, Wkv, bkv, kv + (size_t)l * NN * 2 * DD, NN, 2 * DD, DD, 0);
    }

    for (int l = 0; l < LL; l++) {
        const float* xin = (l == 0) ? expr : x;
        const float* Wq = ipw + (size_t)l * 3 * DD * DD;
        const float* bq = ipb + (size_t)l * 3 * DD;

        run_gemm(xin, Wq, bq, q, NN, DD, DD, 0);

        attn_kernel<<<(NN + 1) / 2, 256>>>(q, kv + (size_t)l * NN * 2 * DD, ao);

        run_gemm(ao, opw + (size_t)l * DD * DD, opb + (size_t)l * DD,
                 tmp, NN, DD, DD, 0);

        add_ln_kernel<<<NN, DD>>>(xin, tmp, ln1g + (size_t)l * DD,
                                  ln1b + (size_t)l * DD, x);

        run_gemm(x, w1 + (size_t)l * 2 * DD * DD, b1 + (size_t)l * 2 * DD,
                 h, NN, 2 * DD, DD, 1);
        run_gemm(h, w2 + (size_t)l * DD * 2 * DD, b2 + (size_t)l * DD,
                 tmp, NN, DD, 2 * DD, 0);

        float* xo = (l == LL - 1) ? out : x;
        add_ln_kernel<<<NN, DD>>>(x, tmp, ln2g + (size_t)l * DD,
                                  ln2b + (size_t)l * DD, xo);
    }
}

// round 16
// speedup vs baseline: 1.2161x; 1.0801x over previous
#include <cuda_runtime.h>
#include <stdint.h>
#include <math.h>

#define NN 20000
#define DD 256
#define HH 4
#define DHH 64
#define LL 2
#define EE 320000
#define KK 48
#define LN_EPS 1e-5f

// ---------------- scratch (static device globals; no allocation) -------------
__device__ float g_kv[LL][(size_t)NN * 2 * DD];   // per row: K[0:256) V[256:512)
__device__ float g_q[(size_t)NN * DD];
__device__ float g_x[(size_t)NN * DD];
__device__ float g_ao[(size_t)NN * DD];
__device__ float g_h[(size_t)NN * 2 * DD];
__device__ int   g_counts[NN];
__device__ int   g_cnt[NN];
__device__ int   g_nbr[NN * KK];

// ---------------- neighbor build --------------------------------------------
__global__ void nbr_init_kernel() {
    int i = blockIdx.x * blockDim.x + threadIdx.x;
    if (i < NN) g_counts[i] = 0;
}

__global__ void nbr_scatter_kernel(const int* __restrict__ ei) {
    int e = blockIdx.x * blockDim.x + threadIdx.x;
    if (e >= EE) return;
    int s = ei[e];
    int t = ei[EE + e];
    int p = atomicAdd(&g_counts[t], 1);
    if (p < KK) g_nbr[t * KK + p] = s;
}

__global__ void nbr_fin_kernel() {
    int n = blockIdx.x * blockDim.x + threadIdx.x;
    if (n >= NN) return;
    int c = g_counts[n];
    if (c == 0) { g_nbr[n * KK] = n; c = 1; }
    g_cnt[n] = (c < KK) ? c : KK;
}

// ---------------- common helpers --------------------------------------------
__device__ __forceinline__ unsigned f2tf(float x) {
    unsigned r;
    asm("cvt.rna.tf32.f32 %0, %1;" : "=r"(r) : "f"(x));
    return r;
}

__device__ __forceinline__ uint32_t smem_u32(const void* p) {
    uint32_t a;
    asm("{ .reg .u64 t; cvta.to.shared.u64 t, %1; cvt.u32.u64 %0, t; }"
        : "=r"(a) : "l"(p));
    return a;
}

#define SMS 36

// ---------------- tf32 GEMM, 2-stage cp.async, 2 CTAs/SM (R13-identical) -----
#define TILE_F (128 * SMS)
#define STAGE_F (2 * TILE_F)
#define GEMM_SMEM_BYTES (2 * STAGE_F * 4)   // 73728 B

__global__ __launch_bounds__(256, 2) void gemm_tf32_kernel(
        const float* __restrict__ A,
        const float* __restrict__ B,
        const float* __restrict__ bias,
        float* __restrict__ C,
        int M, int Nout, int Kd, int act) {
    extern __shared__ float smem[];
    const uint32_t smem_base = smem_u32(smem);

    const int tid  = threadIdx.x;
    const int wid  = tid >> 5;
    const int lane = tid & 31;
    const int g    = lane >> 2;
    const int tg   = lane & 3;
    const int warp_m = wid & 3;
    const int warp_n = wid >> 2;
    const int m0 = blockIdx.y * 128;
    const int n0 = blockIdx.x * 128;

    const int row_ld = tid >> 3;
    const int col_ld = (tid & 7) * 4;

    const int nk = Kd >> 5;

    auto load_tile = [&](int kt, int s) {
        const int k0 = kt * 32;
        const uint32_t abase = smem_base + (uint32_t)s * STAGE_F * 4;
        const uint32_t bbase = abase + TILE_F * 4;
#pragma unroll
        for (int i = 0; i < 4; i++) {
            int row = row_ld + i * 32;
            int m = m0 + row;
            uint32_t adst = abase + (uint32_t)(row * SMS + col_ld) * 4;
            const float* asrc = A + (size_t)m * Kd + k0 + col_ld;
            int ab = (m < M) ? 16 : 0;
            asm volatile("cp.async.cg.shared.global [%0], [%1], 16, %2;"
                         :: "r"(adst), "l"(asrc), "r"(ab));
            uint32_t bdst = bbase + (uint32_t)(row * SMS + col_ld) * 4;
            const float* bsrc = B + (size_t)(n0 + row) * Kd + k0 + col_ld;
            asm volatile("cp.async.cg.shared.global [%0], [%1], 16, %2;"
                         :: "r"(bdst), "l"(bsrc), "r"(16));
        }
        asm volatile("cp.async.commit_group;");
    };

    load_tile(0, 0);
    if (nk > 1) load_tile(1, 1);

    float acc[2][8][4];
#pragma unroll
    for (int i = 0; i < 2; i++)
#pragma unroll
        for (int j = 0; j < 8; j++)
#pragma unroll
            for (int c = 0; c < 4; c++) acc[i][j][c] = 0.0f;

    for (int kt = 0; kt < nk; kt++) {
        const int s = kt & 1;
        asm volatile("cp.async.wait_group 1;");
        __syncthreads();

        const float* As = smem + (size_t)s * STAGE_F;
        const float* Bs = As + TILE_F;
#pragma unroll
        for (int ks = 0; ks < 4; ks++) {
            const int kk = ks * 8;
            unsigned a[2][4], b[8][2];
#pragma unroll
            for (int mt = 0; mt < 2; mt++) {
                int r = warp_m * 32 + mt * 16 + g;
                a[mt][0] = f2tf(As[r * SMS + kk + tg]);
                a[mt][1] = f2tf(As[(r + 8) * SMS + kk + tg]);
                a[mt][2] = f2tf(As[r * SMS + kk + tg + 4]);
                a[mt][3] = f2tf(As[(r + 8) * SMS + kk + tg + 4]);
            }
#pragma unroll
            for (int nt = 0; nt < 8; nt++) {
                int nb = warp_n * 64 + nt * 8 + g;
                b[nt][0] = f2tf(Bs[nb * SMS + kk + tg]);
                b[nt][1] = f2tf(Bs[nb * SMS + kk + tg + 4]);
            }
#pragma unroll
            for (int mt = 0; mt < 2; mt++)
#pragma unroll
                for (int nt = 0; nt < 8; nt++) {
                    asm volatile(
                        "mma.sync.aligned.m16n8k8.row.col.f32.tf32.tf32.f32 "
                        "{%0,%1,%2,%3}, {%4,%5,%6,%7}, {%8,%9}, {%0,%1,%2,%3};"
                        : "+f"(acc[mt][nt][0]), "+f"(acc[mt][nt][1]),
                          "+f"(acc[mt][nt][2]), "+f"(acc[mt][nt][3])
                        : "r"(a[mt][0]), "r"(a[mt][1]), "r"(a[mt][2]), "r"(a[mt][3]),
                          "r"(b[nt][0]), "r"(b[nt][1]));
                }
        }
        __syncthreads();

        if (kt + 2 < nk) load_tile(kt + 2, s);
    }

#pragma unroll
    for (int mt = 0; mt < 2; mt++) {
        int r0 = m0 + warp_m * 32 + mt * 16 + g;
        int r1 = r0 + 8;
#pragma unroll
        for (int nt = 0; nt < 8; nt++) {
            int cb = n0 + warp_n * 64 + nt * 8 + tg * 2;
            float bv0 = bias[cb], bv1 = bias[cb + 1];
            float v0 = acc[mt][nt][0] + bv0;
            float v1 = acc[mt][nt][1] + bv1;
            float v2 = acc[mt][nt][2] + bv0;
            float v3 = acc[mt][nt][3] + bv1;
            if (act) {
                v0 = 0.5f * v0 * (1.0f + erff(v0 * 0.70710678f));
                v1 = 0.5f * v1 * (1.0f + erff(v1 * 0.70710678f));
                v2 = 0.5f * v2 * (1.0f + erff(v2 * 0.70710678f));
                v3 = 0.5f * v3 * (1.0f + erff(v3 * 0.70710678f));
            }
            if (r0 < M) *(float2*)(C + (size_t)r0 * Nout + cb) = make_float2(v0, v1);
            if (r1 < M) *(float2*)(C + (size_t)r1 * Nout + cb) = make_float2(v2, v3);
        }
    }
}

// ---------------- tf32 GEMM + residual + LayerNorm fused epilogue ------------
// BM=64, BN=256 (= DD, full row), BK=32, 8 warps: warp_m = wid&1, warp_n = wid>>1.
// out[m, :] = LN(xres[m, :] + A[m, :]@B^T + bias)

#define LTILE_A (64 * SMS)              // 2304 floats
#define LTILE_B (256 * SMS)             // 9216 floats
#define LSTAGE  (LTILE_A + LTILE_B)     // 11520 floats
#define GEMMLN_SMEM_BYTES ((2 * LSTAGE + 64 * 4 * 2 + 64 * 2) * 4)   // 94720 B

__global__ __launch_bounds__(256, 2) void gemm_ln_kernel(
        const float* __restrict__ A,
        const float* __restrict__ B,
        const float* __restrict__ bias,
        const float* __restrict__ xres,
        const float* __restrict__ gamma,
        const float* __restrict__ beta,
        float* __restrict__ out,
        int M, int Kd) {
    extern __shared__ float smem[];
    const uint32_t smem_base = smem_u32(smem);
    float* s_sum = smem + 2 * LSTAGE;       // [64][4]
    float* s_sq  = s_sum + 256;             // [64][4]
    float* s_mu  = s_sq + 256;              // [64]
    float* s_rs  = s_mu + 64;               // [64]

    const int tid  = threadIdx.x;
    const int wid  = tid >> 5;
    const int lane = tid & 31;
    const int g    = lane >> 2;
    const int tg   = lane & 3;
    const int warp_m = wid & 1;             // 2 x 32 rows
    const int warp_n = wid >> 1;            // 4 x 64 cols
    const int m0 = blockIdx.x * 64;

    const int row_ld = tid >> 3;
    const int col_ld = (tid & 7) * 4;

    const int nk = Kd >> 5;

    auto load_tile = [&](int kt, int s) {
        const int k0 = kt * 32;
        const uint32_t abase = smem_base + (uint32_t)s * LSTAGE * 4;
        const uint32_t bbase = abase + LTILE_A * 4;
        // A: 64 rows x 32 cols = 512 float4 -> 2 per thread
#pragma unroll
        for (int i = 0; i < 2; i++) {
            int idx = tid + i * 256;
            int row = idx >> 3;
            int m = m0 + row;
            uint32_t adst = abase + (uint32_t)(row * SMS + col_ld) * 4;
            const float* asrc = A + (size_t)m * Kd + k0 + col_ld;
            int ab = (m < M) ? 16 : 0;
            asm volatile("cp.async.cg.shared.global [%0], [%1], 16, %2;"
                         :: "r"(adst), "l"(asrc), "r"(ab));
        }
        // B: 256 rows x 32 cols = 2048 float4 -> 8 per thread
#pragma unroll
        for (int i = 0; i < 8; i++) {
            int idx = tid + i * 256;
            int row = idx >> 3;
            uint32_t bdst = bbase + (uint32_t)(row * SMS + col_ld) * 4;
            const float* bsrc = B + (size_t)row * Kd + k0 + col_ld;
            asm volatile("cp.async.cg.shared.global [%0], [%1], 16, %2;"
                         :: "r"(bdst), "l"(bsrc), "r"(16));
        }
        asm volatile("cp.async.commit_group;");
    };

    load_tile(0, 0);
    if (nk > 1) load_tile(1, 1);

    float acc[2][8][4];
#pragma unroll
    for (int i = 0; i < 2; i++)
#pragma unroll
        for (int j = 0; j < 8; j++)
#pragma unroll
            for (int c = 0; c < 4; c++) acc[i][j][c] = 0.0f;

    for (int kt = 0; kt < nk; kt++) {
        const int s = kt & 1;
        asm volatile("cp.async.wait_group 1;");
        __syncthreads();

        const float* As = smem + (size_t)s * LSTAGE;
        const float* Bs = As + LTILE_A;
#pragma unroll
        for (int ks = 0; ks < 4; ks++) {
            const int kk = ks * 8;
            unsigned a[2][4], b[8][2];
#pragma unroll
            for (int mt = 0; mt < 2; mt++) {
                int r = warp_m * 32 + mt * 16 + g;
                a[mt][0] = f2tf(As[r * SMS + kk + tg]);
                a[mt][1] = f2tf(As[(r + 8) * SMS + kk + tg]);
                a[mt][2] = f2tf(As[r * SMS + kk + tg + 4]);
                a[mt][3] = f2tf(As[(r + 8) * SMS + kk + tg + 4]);
            }
#pragma unroll
            for (int nt = 0; nt < 8; nt++) {
                int nb = warp_n * 64 + nt * 8 + g;
                b[nt][0] = f2tf(Bs[nb * SMS + kk + tg]);
                b[nt][1] = f2tf(Bs[nb * SMS + kk + tg + 4]);
            }
#pragma unroll
            for (int mt = 0; mt < 2; mt++)
#pragma unroll
                for (int nt = 0; nt < 8; nt++) {
                    asm volatile(
                        "mma.sync.aligned.m16n8k8.row.col.f32.tf32.tf32.f32 "
                        "{%0,%1,%2,%3}, {%4,%5,%6,%7}, {%8,%9}, {%0,%1,%2,%3};"
                        : "+f"(acc[mt][nt][0]), "+f"(acc[mt][nt][1]),
                          "+f"(acc[mt][nt][2]), "+f"(acc[mt][nt][3])
                        : "r"(a[mt][0]), "r"(a[mt][1]), "r"(a[mt][2]), "r"(a[mt][3]),
                          "r"(b[nt][0]), "r"(b[nt][1]));
                }
        }
        __syncthreads();

        if (kt + 2 < nk) load_tile(kt + 2, s);
    }

    // ---- epilogue: bias + residual, per-row LN, write -----------------------
    // add bias + residual in place; accumulate per-row partial sums
    float rsum[2][2], rsq[2][2];
#pragma unroll
    for (int mt = 0; mt < 2; mt++) {
        int r0 = warp_m * 32 + mt * 16 + g;
        int r1 = r0 + 8;
        int gm0 = m0 + r0, gm1 = m0 + r1;
        float s0 = 0.f, q0 = 0.f, s1 = 0.f, q1 = 0.f;
#pragma unroll
        for (int nt = 0; nt < 8; nt++) {
            int cb = warp_n * 64 + nt * 8 + tg * 2;
            float bv0 = bias[cb], bv1 = bias[cb + 1];
            float2 xr0 = (gm0 < M) ? *(const float2*)(xres + (size_t)gm0 * DD + cb)
                                   : make_float2(0.f, 0.f);
            float2 xr1 = (gm1 < M) ? *(const float2*)(xres + (size_t)gm1 * DD + cb)
                                   : make_float2(0.f, 0.f);
            float v0 = acc[mt][nt][0] + bv0 + xr0.x;
            float v1 = acc[mt][nt][1] + bv1 + xr0.y;
            float v2 = acc[mt][nt][2] + bv0 + xr1.x;
            float v3 = acc[mt][nt][3] + bv1 + xr1.y;
            acc[mt][nt][0] = v0; acc[mt][nt][1] = v1;
            acc[mt][nt][2] = v2; acc[mt][nt][3] = v3;
            s0 += v0 + v1; q0 += v0 * v0 + v1 * v1;
            s1 += v2 + v3; q1 += v2 * v2 + v3 * v3;
        }
        rsum[mt][0] = s0; rsq[mt][0] = q0;
        rsum[mt][1] = s1; rsq[mt][1] = q1;
    }

    // reduce over tg (4 lanes of same g share a row)
#pragma unroll
    for (int mt = 0; mt < 2; mt++)
#pragma unroll
        for (int rr = 0; rr < 2; rr++) {
            float s = rsum[mt][rr], q = rsq[mt][rr];
            s += __shfl_xor_sync(0xffffffffu, s, 1);
            s += __shfl_xor_sync(0xffffffffu, s, 2);
            q += __shfl_xor_sync(0xffffffffu, q, 1);
            q += __shfl_xor_sync(0xffffffffu, q, 2);
            rsum[mt][rr] = s; rsq[mt][rr] = q;
        }
    if (tg == 0) {
#pragma unroll
        for (int mt = 0; mt < 2; mt++)
#pragma unroll
            for (int rr = 0; rr < 2; rr++) {
                int r = warp_m * 32 + mt * 16 + rr * 8 + g;
                s_sum[r * 4 + warp_n] = rsum[mt][rr];
                s_sq[r * 4 + warp_n]  = rsq[mt][rr];
            }
    }
    __syncthreads();

    if (tid < 64) {
        float S = s_sum[tid * 4] + s_sum[tid * 4 + 1] + s_sum[tid * 4 + 2] + s_sum[tid * 4 + 3];
        float Q = s_sq[tid * 4]  + s_sq[tid * 4 + 1]  + s_sq[tid * 4 + 2]  + s_sq[tid * 4 + 3];
        float mu  = S * (1.0f / DD);
        float var = Q * (1.0f / DD) - mu * mu;
        s_mu[tid] = mu;
        s_rs[tid] = rsqrtf(var + LN_EPS);
    }
    __syncthreads();

#pragma unroll
    for (int mt = 0; mt < 2; mt++) {
        int r0 = warp_m * 32 + mt * 16 + g;
        int r1 = r0 + 8;
        int gm0 = m0 + r0, gm1 = m0 + r1;
        float mu0 = s_mu[r0], rv0 = s_rs[r0];
        float mu1 = s_mu[r1], rv1 = s_rs[r1];
#pragma unroll
        for (int nt = 0; nt < 8; nt++) {
            int cb = warp_n * 64 + nt * 8 + tg * 2;
            float g0 = gamma[cb], g1 = gamma[cb + 1];
            float b0 = beta[cb],  b1 = beta[cb + 1];
            if (gm0 < M) {
                float2 o;
                o.x = (acc[mt][nt][0] - mu0) * rv0 * g0 + b0;
                o.y = (acc[mt][nt][1] - mu0) * rv0 * g1 + b1;
                *(float2*)(out + (size_t)gm0 * DD + cb) = o;
            }
            if (gm1 < M) {
                float2 o;
                o.x = (acc[mt][nt][2] - mu1) * rv1 * g0 + b0;
                o.y = (acc[mt][nt][3] - mu1) * rv1 * g1 + b1;
                *(float2*)(out + (size_t)gm1 * DD + cb) = o;
            }
        }
    }
}

// ---------------- attention: 2 nodes/block, one warp per (node,head) --------
__global__ __launch_bounds__(256) void attn_kernel(
        const float* __restrict__ q,
        const float* __restrict__ kv,
        float* __restrict__ ao) {
    const int local = threadIdx.x >> 7;
    const int n = blockIdx.x * 2 + local;
    const int warp = (threadIdx.x >> 5) & 3;
    const int lane = threadIdx.x & 31;

    __shared__ float s_sc[2][HH][KK];
    __shared__ int   s_nbr[2][KK];
    __shared__ int   s_cnt[2];

    if (n < NN) {
        const int t = threadIdx.x & 127;
        if (t == 0) s_cnt[local] = g_cnt[n];
        for (int j = t; j < KK; j += 128) s_nbr[local][j] = g_nbr[n * KK + j];
    }
    __syncthreads();
    if (n >= NN) return;
    const int cnt = s_cnt[local];

    const int sub = lane >> 3;
    const int lr  = lane & 7;

    const float4* qb = (const float4*)(q + (size_t)n * DD + warp * DHH + lr * 8);
    float4 q0 = qb[0], q1 = qb[1];

    for (int j0 = 0; j0 < cnt; j0 += 4) {
        int j = j0 + sub;
        float dot = 0.0f;
        if (j < cnt) {
            const float4* kp = (const float4*)(kv + (size_t)s_nbr[local][j] * (2 * DD) + warp * DHH + lr * 8);
            float4 k0 = kp[0], k1 = kp[1];
            dot = q0.x * k0.x + q0.y * k0.y + q0.z * k0.z + q0.w * k0.w
                + q1.x * k1.x + q1.y * k1.y + q1.z * k1.z + q1.w * k1.w;
        }
        dot += __shfl_xor_sync(0xffffffffu, dot, 1);
        dot += __shfl_xor_sync(0xffffffffu, dot, 2);
        dot += __shfl_xor_sync(0xffffffffu, dot, 4);
        if (lr == 0 && j < cnt) s_sc[local][warp][j] = dot * 0.125f;
    }
    __syncwarp();

    float a0 = (lane < cnt) ? s_sc[local][warp][lane] : -1e30f;
    float a1 = (lane + 32 < cnt) ? s_sc[local][warp][lane + 32] : -1e30f;
    float mx = fmaxf(a0, a1);
#pragma unroll
    for (int o = 16; o; o >>= 1) mx = fmaxf(mx, __shfl_xor_sync(0xffffffffu, mx, o));
    float e0 = (lane < cnt) ? __expf(a0 - mx) : 0.0f;
    float e1 = (lane + 32 < cnt) ? __expf(a1 - mx) : 0.0f;
    float s = e0 + e1;
#pragma unroll
    for (int o = 16; o; o >>= 1) s += __shfl_xor_sync(0xffffffffu, s, o);
    float inv = 1.0f / s;
    s_sc[local][warp][lane] = e0 * inv;
    if (lane + 32 < KK) s_sc[local][warp][lane + 32] = e1 * inv;
    __syncwarp();

    float2 acc = {0.0f, 0.0f};
    for (int j = 0; j < cnt; j++) {
        float w = s_sc[local][warp][j];
        const float2* vp = (const float2*)(kv + (size_t)s_nbr[local][j] * (2 * DD) + DD + warp * DHH);
        float2 vv = vp[lane];
        acc.x += w * vv.x;
        acc.y += w * vv.y;
    }
    ((float2*)(ao + (size_t)n * DD + warp * DHH))[lane] = acc;
}

// ---------------- launch -----------------------------------------------------
static inline void run_gemm(const float* A, const float* B, const float* bias,
                            float* C, int M, int Nout, int Kd, int act) {
    dim3 grid(Nout / 128, (M + 127) / 128);
    gemm_tf32_kernel<<<grid, 256, GEMM_SMEM_BYTES>>>(A, B, bias, C, M, Nout, Kd, act);
}

static inline void run_gemm_ln(const float* A, const float* B, const float* bias,
                               const float* xres, const float* gamma, const float* beta,
                               float* out, int Kd) {
    gemm_ln_kernel<<<(NN + 63) / 64, 256, GEMMLN_SMEM_BYTES>>>(
        A, B, bias, xres, gamma, beta, out, NN, Kd);
}

extern "C" void kernel_launch(void* const* d_in, const int* in_sizes, int n_in,
                              void* d_out, int out_size) {
    const float* expr    = (const float*)d_in[0];
    const float* spatial = (const float*)d_in[1];
    const float* ipw     = (const float*)d_in[2];
    const float* ipb     = (const float*)d_in[3];
    const float* opw     = (const float*)d_in[4];
    const float* opb     = (const float*)d_in[5];
    const float* w1      = (const float*)d_in[6];
    const float* b1      = (const float*)d_in[7];
    const float* w2      = (const float*)d_in[8];
    const float* b2      = (const float*)d_in[9];
    const float* ln1g    = (const float*)d_in[10];
    const float* ln1b    = (const float*)d_in[11];
    const float* ln2g    = (const float*)d_in[12];
    const float* ln2b    = (const float*)d_in[13];
    const int*   ei      = (const int*)d_in[14];
    float* out = (float*)d_out;

    static int smem_set = 0;
    if (!smem_set) {
        cudaFuncSetAttribute(gemm_tf32_kernel,
                             cudaFuncAttributeMaxDynamicSharedMemorySize,
                             GEMM_SMEM_BYTES);
        cudaFuncSetAttribute(gemm_ln_kernel,
                             cudaFuncAttributeMaxDynamicSharedMemorySize,
                             GEMMLN_SMEM_BYTES);
        smem_set = 1;
    }

    float *kv, *q, *x, *ao, *h;
    cudaGetSymbolAddress((void**)&kv, g_kv);
    cudaGetSymbolAddress((void**)&q,  g_q);
    cudaGetSymbolAddress((void**)&x,  g_x);
    cudaGetSymbolAddress((void**)&ao, g_ao);
    cudaGetSymbolAddress((void**)&h,  g_h);

    nbr_init_kernel<<<(NN + 255) / 256, 256>>>();
    nbr_scatter_kernel<<<(EE + 255) / 256, 256>>>(ei);
    nbr_fin_kernel<<<(NN + 255) / 256, 256>>>();

    // fused K+V projection: rows [D, 3D) of in_proj are [Wk; Wv] (512 x 256)
    for (int l = 0; l < LL; l++) {
        const float* Wkv = ipw + ((size_t)l * 3 * DD + DD) * DD;
        const float* bkv = ipb + (size_t)l * 3 * DD + DD;
        run_gemm(spatial, Wkv, bkv, kv + (size_t)l * NN * 2 * DD, NN, 2 * DD, DD, 0);
    }

    for (int l = 0; l < LL; l++) {
        const float* xin = (l == 0) ? expr : x;
        const float* Wq = ipw + (size_t)l * 3 * DD * DD;
        const float* bq = ipb + (size_t)l * 3 * DD;

        run_gemm(xin, Wq, bq, q, NN, DD, DD, 0);

        attn_kernel<<<(NN + 1) / 2, 256>>>(q, kv + (size_t)l * NN * 2 * DD, ao);

        // attn-out GEMM fused with residual + LN1 -> x
        run_gemm_ln(ao, opw + (size_t)l * DD * DD, opb + (size_t)l * DD,
                    xin, ln1g + (size_t)l * DD, ln1b + (size_t)l * DD, x, DD);

        run_gemm(x, w1 + (size_t)l * 2 * DD * DD, b1 + (size_t)l * 2 * DD,
                 h, NN, 2 * DD, DD, 1);

        // W2 GEMM fused with residual + LN2 -> x (or final out)
        float* xo = (l == LL - 1) ? out : x;
        run_gemm_ln(h, w2 + (size_t)l * DD * 2 * DD, b2 + (size_t)l * DD,
                    x, ln2g + (size_t)l * DD, ln2b + (size_t)l * DD, xo, 2 * DD);
    }
}

// round 17
// speedup vs baseline: 1.2531x; 1.0305x over previous
#include <cuda_runtime.h>
#include <stdint.h>
#include <math.h>

#define NN 20000
#define DD 256
#define HH 4
#define DHH 64
#define LL 2
#define EE 320000
#define KK 48
#define LN_EPS 1e-5f

// ---------------- scratch (static device globals; no allocation) -------------
__device__ float g_kv[LL][(size_t)NN * 2 * DD];   // per row: K[0:256) V[256:512)
__device__ float g_q[(size_t)NN * DD];
__device__ float g_x[(size_t)NN * DD];
__device__ float g_ao[(size_t)NN * DD];
__device__ float g_h[(size_t)NN * 2 * DD];
__device__ int   g_counts[NN];
__device__ int   g_cnt[NN];
__device__ int   g_nbr[NN * KK];

// ---------------- neighbor build --------------------------------------------
__global__ void nbr_init_kernel() {
    int i = blockIdx.x * blockDim.x + threadIdx.x;
    if (i < NN) g_counts[i] = 0;
}

__global__ void nbr_scatter_kernel(const int* __restrict__ ei) {
    int e = blockIdx.x * blockDim.x + threadIdx.x;
    if (e >= EE) return;
    int s = ei[e];
    int t = ei[EE + e];
    int p = atomicAdd(&g_counts[t], 1);
    if (p < KK) g_nbr[t * KK + p] = s;
}

__global__ void nbr_fin_kernel() {
    int n = blockIdx.x * blockDim.x + threadIdx.x;
    if (n >= NN) return;
    int c = g_counts[n];
    if (c == 0) { g_nbr[n * KK] = n; c = 1; }
    g_cnt[n] = (c < KK) ? c : KK;
}

// ---------------- common helpers --------------------------------------------
__device__ __forceinline__ unsigned f2tf(float x) {
    unsigned r;
    asm("cvt.rna.tf32.f32 %0, %1;" : "=r"(r) : "f"(x));
    return r;
}

__device__ __forceinline__ uint32_t smem_u32(const void* p) {
    uint32_t a;
    asm("{ .reg .u64 t; cvta.to.shared.u64 t, %1; cvt.u32.u64 %0, t; }"
        : "=r"(a) : "l"(p));
    return a;
}

#define SMS 36
#define TILE_F (128 * SMS)
#define STAGE_F (2 * TILE_F)
#define GEMM_SMEM_BYTES (2 * STAGE_F * 4)   // 73728 B

// ---------------- shared GEMM body (tile at m0,n0) ---------------------------
__device__ __forceinline__ void gemm_tile_body(
        const float* __restrict__ A,
        const float* __restrict__ B,
        const float* __restrict__ bias,
        float* __restrict__ C,
        int M, int Nout, int Kd, int act,
        int m0, int n0, float* smem, uint32_t smem_base) {
    const int tid  = threadIdx.x;
    const int wid  = tid >> 5;
    const int lane = tid & 31;
    const int g    = lane >> 2;
    const int tg   = lane & 3;
    const int warp_m = wid & 3;
    const int warp_n = wid >> 2;

    const int row_ld = tid >> 3;
    const int col_ld = (tid & 7) * 4;

    const int nk = Kd >> 5;

    auto load_tile = [&](int kt, int s) {
        const int k0 = kt * 32;
        const uint32_t abase = smem_base + (uint32_t)s * STAGE_F * 4;
        const uint32_t bbase = abase + TILE_F * 4;
#pragma unroll
        for (int i = 0; i < 4; i++) {
            int row = row_ld + i * 32;
            int m = m0 + row;
            uint32_t adst = abase + (uint32_t)(row * SMS + col_ld) * 4;
            const float* asrc = A + (size_t)m * Kd + k0 + col_ld;
            int ab = (m < M) ? 16 : 0;
            asm volatile("cp.async.cg.shared.global [%0], [%1], 16, %2;"
                         :: "r"(adst), "l"(asrc), "r"(ab));
            uint32_t bdst = bbase + (uint32_t)(row * SMS + col_ld) * 4;
            const float* bsrc = B + (size_t)(n0 + row) * Kd + k0 + col_ld;
            asm volatile("cp.async.cg.shared.global [%0], [%1], 16, %2;"
                         :: "r"(bdst), "l"(bsrc), "r"(16));
        }
        asm volatile("cp.async.commit_group;");
    };

    load_tile(0, 0);
    if (nk > 1) load_tile(1, 1);

    float acc[2][8][4];
#pragma unroll
    for (int i = 0; i < 2; i++)
#pragma unroll
        for (int j = 0; j < 8; j++)
#pragma unroll
            for (int c = 0; c < 4; c++) acc[i][j][c] = 0.0f;

    for (int kt = 0; kt < nk; kt++) {
        const int s = kt & 1;
        asm volatile("cp.async.wait_group 1;");
        __syncthreads();

        const float* As = smem + (size_t)s * STAGE_F;
        const float* Bs = As + TILE_F;
#pragma unroll
        for (int ks = 0; ks < 4; ks++) {
            const int kk = ks * 8;
            unsigned a[2][4], b[8][2];
#pragma unroll
            for (int mt = 0; mt < 2; mt++) {
                int r = warp_m * 32 + mt * 16 + g;
                a[mt][0] = f2tf(As[r * SMS + kk + tg]);
                a[mt][1] = f2tf(As[(r + 8) * SMS + kk + tg]);
                a[mt][2] = f2tf(As[r * SMS + kk + tg + 4]);
                a[mt][3] = f2tf(As[(r + 8) * SMS + kk + tg + 4]);
            }
#pragma unroll
            for (int nt = 0; nt < 8; nt++) {
                int nb = warp_n * 64 + nt * 8 + g;
                b[nt][0] = f2tf(Bs[nb * SMS + kk + tg]);
                b[nt][1] = f2tf(Bs[nb * SMS + kk + tg + 4]);
            }
#pragma unroll
            for (int mt = 0; mt < 2; mt++)
#pragma unroll
                for (int nt = 0; nt < 8; nt++) {
                    asm volatile(
                        "mma.sync.aligned.m16n8k8.row.col.f32.tf32.tf32.f32 "
                        "{%0,%1,%2,%3}, {%4,%5,%6,%7}, {%8,%9}, {%0,%1,%2,%3};"
                        : "+f"(acc[mt][nt][0]), "+f"(acc[mt][nt][1]),
                          "+f"(acc[mt][nt][2]), "+f"(acc[mt][nt][3])
                        : "r"(a[mt][0]), "r"(a[mt][1]), "r"(a[mt][2]), "r"(a[mt][3]),
                          "r"(b[nt][0]), "r"(b[nt][1]));
                }
        }
        __syncthreads();

        if (kt + 2 < nk) load_tile(kt + 2, s);
    }

#pragma unroll
    for (int mt = 0; mt < 2; mt++) {
        int r0 = m0 + warp_m * 32 + mt * 16 + g;
        int r1 = r0 + 8;
#pragma unroll
        for (int nt = 0; nt < 8; nt++) {
            int cb = n0 + warp_n * 64 + nt * 8 + tg * 2;
            float bv0 = bias[cb], bv1 = bias[cb + 1];
            float v0 = acc[mt][nt][0] + bv0;
            float v1 = acc[mt][nt][1] + bv1;
            float v2 = acc[mt][nt][2] + bv0;
            float v3 = acc[mt][nt][3] + bv1;
            if (act) {
                v0 = 0.5f * v0 * (1.0f + erff(v0 * 0.70710678f));
                v1 = 0.5f * v1 * (1.0f + erff(v1 * 0.70710678f));
                v2 = 0.5f * v2 * (1.0f + erff(v2 * 0.70710678f));
                v3 = 0.5f * v3 * (1.0f + erff(v3 * 0.70710678f));
            }
            if (r0 < M) *(float2*)(C + (size_t)r0 * Nout + cb) = make_float2(v0, v1);
            if (r1 < M) *(float2*)(C + (size_t)r1 * Nout + cb) = make_float2(v2, v3);
        }
    }
}

// ---------------- single-matrix GEMM launch ----------------------------------
__global__ __launch_bounds__(256, 2) void gemm_tf32_kernel(
        const float* __restrict__ A, const float* __restrict__ B,
        const float* __restrict__ bias, float* __restrict__ C,
        int M, int Nout, int Kd, int act) {
    extern __shared__ float smem[];
    gemm_tile_body(A, B, bias, C, M, Nout, Kd, act,
                   blockIdx.y * 128, blockIdx.x * 128, smem, smem_u32(smem));
}

// ---------------- 3-segment fused GEMM launch (independent projections) ------
struct Seg { const float* A; const float* B; const float* bias; float* C; int ntx; int tile_end; };

__global__ __launch_bounds__(256, 2) void gemm3_kernel(Seg s0, Seg s1, Seg s2) {
    extern __shared__ float smem[];
    int t = blockIdx.x;
    Seg s = (t < s0.tile_end) ? s0 : (t < s1.tile_end) ? s1 : s2;
    int base = (t < s0.tile_end) ? 0 : (t < s1.tile_end) ? s0.tile_end : s1.tile_end;
    int lt = t - base;
    int bx = lt % s.ntx;
    int by = lt / s.ntx;
    gemm_tile_body(s.A, s.B, s.bias, s.C, NN, s.ntx * 128, DD, 0,
                   by * 128, bx * 128, smem, smem_u32(smem));
}

// ---------------- tf32 GEMM + residual + LayerNorm fused epilogue ------------
#define LTILE_A (64 * SMS)
#define LTILE_B (256 * SMS)
#define LSTAGE  (LTILE_A + LTILE_B)
#define GEMMLN_SMEM_BYTES ((2 * LSTAGE + 64 * 4 * 2 + 64 * 2) * 4)   // 94720 B

__global__ __launch_bounds__(256, 2) void gemm_ln_kernel(
        const float* __restrict__ A,
        const float* __restrict__ B,
        const float* __restrict__ bias,
        const float* __restrict__ xres,
        const float* __restrict__ gamma,
        const float* __restrict__ beta,
        float* __restrict__ out,
        int M, int Kd) {
    extern __shared__ float smem[];
    const uint32_t smem_base = smem_u32(smem);
    float* s_sum = smem + 2 * LSTAGE;
    float* s_sq  = s_sum + 256;
    float* s_mu  = s_sq + 256;
    float* s_rs  = s_mu + 64;

    const int tid  = threadIdx.x;
    const int wid  = tid >> 5;
    const int lane = tid & 31;
    const int g    = lane >> 2;
    const int tg   = lane & 3;
    const int warp_m = wid & 1;
    const int warp_n = wid >> 1;
    const int m0 = blockIdx.x * 64;

    const int col_ld = (tid & 7) * 4;

    const int nk = Kd >> 5;

    auto load_tile = [&](int kt, int s) {
        const int k0 = kt * 32;
        const uint32_t abase = smem_base + (uint32_t)s * LSTAGE * 4;
        const uint32_t bbase = abase + LTILE_A * 4;
#pragma unroll
        for (int i = 0; i < 2; i++) {
            int idx = tid + i * 256;
            int row = idx >> 3;
            int m = m0 + row;
            uint32_t adst = abase + (uint32_t)(row * SMS + col_ld) * 4;
            const float* asrc = A + (size_t)m * Kd + k0 + col_ld;
            int ab = (m < M) ? 16 : 0;
            asm volatile("cp.async.cg.shared.global [%0], [%1], 16, %2;"
                         :: "r"(adst), "l"(asrc), "r"(ab));
        }
#pragma unroll
        for (int i = 0; i < 8; i++) {
            int idx = tid + i * 256;
            int row = idx >> 3;
            uint32_t bdst = bbase + (uint32_t)(row * SMS + col_ld) * 4;
            const float* bsrc = B + (size_t)row * Kd + k0 + col_ld;
            asm volatile("cp.async.cg.shared.global [%0], [%1], 16, %2;"
                         :: "r"(bdst), "l"(bsrc), "r"(16));
        }
        asm volatile("cp.async.commit_group;");
    };

    load_tile(0, 0);
    if (nk > 1) load_tile(1, 1);

    float acc[2][8][4];
#pragma unroll
    for (int i = 0; i < 2; i++)
#pragma unroll
        for (int j = 0; j < 8; j++)
#pragma unroll
            for (int c = 0; c < 4; c++) acc[i][j][c] = 0.0f;

    for (int kt = 0; kt < nk; kt++) {
        const int s = kt & 1;
        asm volatile("cp.async.wait_group 1;");
        __syncthreads();

        const float* As = smem + (size_t)s * LSTAGE;
        const float* Bs = As + LTILE_A;
#pragma unroll
        for (int ks = 0; ks < 4; ks++) {
            const int kk = ks * 8;
            unsigned a[2][4], b[8][2];
#pragma unroll
            for (int mt = 0; mt < 2; mt++) {
                int r = warp_m * 32 + mt * 16 + g;
                a[mt][0] = f2tf(As[r * SMS + kk + tg]);
                a[mt][1] = f2tf(As[(r + 8) * SMS + kk + tg]);
                a[mt][2] = f2tf(As[r * SMS + kk + tg + 4]);
                a[mt][3] = f2tf(As[(r + 8) * SMS + kk + tg + 4]);
            }
#pragma unroll
            for (int nt = 0; nt < 8; nt++) {
                int nb = warp_n * 64 + nt * 8 + g;
                b[nt][0] = f2tf(Bs[nb * SMS + kk + tg]);
                b[nt][1] = f2tf(Bs[nb * SMS + kk + tg + 4]);
            }
#pragma unroll
            for (int mt = 0; mt < 2; mt++)
#pragma unroll
                for (int nt = 0; nt < 8; nt++) {
                    asm volatile(
                        "mma.sync.aligned.m16n8k8.row.col.f32.tf32.tf32.f32 "
                        "{%0,%1,%2,%3}, {%4,%5,%6,%7}, {%8,%9}, {%0,%1,%2,%3};"
                        : "+f"(acc[mt][nt][0]), "+f"(acc[mt][nt][1]),
                          "+f"(acc[mt][nt][2]), "+f"(acc[mt][nt][3])
                        : "r"(a[mt][0]), "r"(a[mt][1]), "r"(a[mt][2]), "r"(a[mt][3]),
                          "r"(b[nt][0]), "r"(b[nt][1]));
                }
        }
        __syncthreads();

        if (kt + 2 < nk) load_tile(kt + 2, s);
    }

    float rsum[2][2], rsq[2][2];
#pragma unroll
    for (int mt = 0; mt < 2; mt++) {
        int r0 = warp_m * 32 + mt * 16 + g;
        int r1 = r0 + 8;
        int gm0 = m0 + r0, gm1 = m0 + r1;
        float s0 = 0.f, q0 = 0.f, s1 = 0.f, q1 = 0.f;
#pragma unroll
        for (int nt = 0; nt < 8; nt++) {
            int cb = warp_n * 64 + nt * 8 + tg * 2;
            float bv0 = bias[cb], bv1 = bias[cb + 1];
            float2 xr0 = (gm0 < M) ? *(const float2*)(xres + (size_t)gm0 * DD + cb)
                                   : make_float2(0.f, 0.f);
            float2 xr1 = (gm1 < M) ? *(const float2*)(xres + (size_t)gm1 * DD + cb)
                                   : make_float2(0.f, 0.f);
            float v0 = acc[mt][nt][0] + bv0 + xr0.x;
            float v1 = acc[mt][nt][1] + bv1 + xr0.y;
            float v2 = acc[mt][nt][2] + bv0 + xr1.x;
            float v3 = acc[mt][nt][3] + bv1 + xr1.y;
            acc[mt][nt][0] = v0; acc[mt][nt][1] = v1;
            acc[mt][nt][2] = v2; acc[mt][nt][3] = v3;
            s0 += v0 + v1; q0 += v0 * v0 + v1 * v1;
            s1 += v2 + v3; q1 += v2 * v2 + v3 * v3;
        }
        rsum[mt][0] = s0; rsq[mt][0] = q0;
        rsum[mt][1] = s1; rsq[mt][1] = q1;
    }

#pragma unroll
    for (int mt = 0; mt < 2; mt++)
#pragma unroll
        for (int rr = 0; rr < 2; rr++) {
            float s = rsum[mt][rr], q = rsq[mt][rr];
            s += __shfl_xor_sync(0xffffffffu, s, 1);
            s += __shfl_xor_sync(0xffffffffu, s, 2);
            q += __shfl_xor_sync(0xffffffffu, q, 1);
            q += __shfl_xor_sync(0xffffffffu, q, 2);
            rsum[mt][rr] = s; rsq[mt][rr] = q;
        }
    if (tg == 0) {
#pragma unroll
        for (int mt = 0; mt < 2; mt++)
#pragma unroll
            for (int rr = 0; rr < 2; rr++) {
                int r = warp_m * 32 + mt * 16 + rr * 8 + g;
                s_sum[r * 4 + warp_n] = rsum[mt][rr];
                s_sq[r * 4 + warp_n]  = rsq[mt][rr];
            }
    }
    __syncthreads();

    if (tid < 64) {
        float S = s_sum[tid * 4] + s_sum[tid * 4 + 1] + s_sum[tid * 4 + 2] + s_sum[tid * 4 + 3];
        float Q = s_sq[tid * 4]  + s_sq[tid * 4 + 1]  + s_sq[tid * 4 + 2]  + s_sq[tid * 4 + 3];
        float mu  = S * (1.0f / DD);
        float var = Q * (1.0f / DD) - mu * mu;
        s_mu[tid] = mu;
        s_rs[tid] = rsqrtf(var + LN_EPS);
    }
    __syncthreads();

#pragma unroll
    for (int mt = 0; mt < 2; mt++) {
        int r0 = warp_m * 32 + mt * 16 + g;
        int r1 = r0 + 8;
        int gm0 = m0 + r0, gm1 = m0 + r1;
        float mu0 = s_mu[r0], rv0 = s_rs[r0];
        float mu1 = s_mu[r1], rv1 = s_rs[r1];
#pragma unroll
        for (int nt = 0; nt < 8; nt++) {
            int cb = warp_n * 64 + nt * 8 + tg * 2;
            float g0 = gamma[cb], g1 = gamma[cb + 1];
            float b0 = beta[cb],  b1 = beta[cb + 1];
            if (gm0 < M) {
                float2 o;
                o.x = (acc[mt][nt][0] - mu0) * rv0 * g0 + b0;
                o.y = (acc[mt][nt][1] - mu0) * rv0 * g1 + b1;
                *(float2*)(out + (size_t)gm0 * DD + cb) = o;
            }
            if (gm1 < M) {
                float2 o;
                o.x = (acc[mt][nt][2] - mu1) * rv1 * g0 + b0;
                o.y = (acc[mt][nt][3] - mu1) * rv1 * g1 + b1;
                *(float2*)(out + (size_t)gm1 * DD + cb) = o;
            }
        }
    }
}

// ---------------- attention: 2 nodes/block, one warp per (node,head) --------
__global__ __launch_bounds__(256) void attn_kernel(
        const float* __restrict__ q,
        const float* __restrict__ kv,
        float* __restrict__ ao) {
    const int local = threadIdx.x >> 7;
    const int n = blockIdx.x * 2 + local;
    const int warp = (threadIdx.x >> 5) & 3;
    const int lane = threadIdx.x & 31;

    __shared__ float s_sc[2][HH][KK];
    __shared__ int   s_nbr[2][KK];
    __shared__ int   s_cnt[2];

    if (n < NN) {
        const int t = threadIdx.x & 127;
        if (t == 0) s_cnt[local] = g_cnt[n];
        for (int j = t; j < KK; j += 128) s_nbr[local][j] = g_nbr[n * KK + j];
    }
    __syncthreads();
    if (n >= NN) return;
    const int cnt = s_cnt[local];

    const int sub = lane >> 3;
    const int lr  = lane & 7;

    const float4* qb = (const float4*)(q + (size_t)n * DD + warp * DHH + lr * 8);
    float4 q0 = qb[0], q1 = qb[1];

    for (int j0 = 0; j0 < cnt; j0 += 4) {
        int j = j0 + sub;
        float dot = 0.0f;
        if (j < cnt) {
            const float4* kp = (const float4*)(kv + (size_t)s_nbr[local][j] * (2 * DD) + warp * DHH + lr * 8);
            float4 k0 = kp[0], k1 = kp[1];
            dot = q0.x * k0.x + q0.y * k0.y + q0.z * k0.z + q0.w * k0.w
                + q1.x * k1.x + q1.y * k1.y + q1.z * k1.z + q1.w * k1.w;
        }
        dot += __shfl_xor_sync(0xffffffffu, dot, 1);
        dot += __shfl_xor_sync(0xffffffffu, dot, 2);
        dot += __shfl_xor_sync(0xffffffffu, dot, 4);
        if (lr == 0 && j < cnt) s_sc[local][warp][j] = dot * 0.125f;
    }
    __syncwarp();

    float a0 = (lane < cnt) ? s_sc[local][warp][lane] : -1e30f;
    float a1 = (lane + 32 < cnt) ? s_sc[local][warp][lane + 32] : -1e30f;
    float mx = fmaxf(a0, a1);
#pragma unroll
    for (int o = 16; o; o >>= 1) mx = fmaxf(mx, __shfl_xor_sync(0xffffffffu, mx, o));
    float e0 = (lane < cnt) ? __expf(a0 - mx) : 0.0f;
    float e1 = (lane + 32 < cnt) ? __expf(a1 - mx) : 0.0f;
    float s = e0 + e1;
#pragma unroll
    for (int o = 16; o; o >>= 1) s += __shfl_xor_sync(0xffffffffu, s, o);
    float inv = 1.0f / s;
    s_sc[local][warp][lane] = e0 * inv;
    if (lane + 32 < KK) s_sc[local][warp][lane + 32] = e1 * inv;
    __syncwarp();

    float2 acc = {0.0f, 0.0f};
    for (int j = 0; j < cnt; j++) {
        float w = s_sc[local][warp][j];
        const float2* vp = (const float2*)(kv + (size_t)s_nbr[local][j] * (2 * DD) + DD + warp * DHH);
        float2 vv = vp[lane];
        acc.x += w * vv.x;
        acc.y += w * vv.y;
    }
    ((float2*)(ao + (size_t)n * DD + warp * DHH))[lane] = acc;
}

// ---------------- launch -----------------------------------------------------
static inline void run_gemm(const float* A, const float* B, const float* bias,
                            float* C, int M, int Nout, int Kd, int act) {
    dim3 grid(Nout / 128, (M + 127) / 128);
    gemm_tf32_kernel<<<grid, 256, GEMM_SMEM_BYTES>>>(A, B, bias, C, M, Nout, Kd, act);
}

static inline void run_gemm_ln(const float* A, const float* B, const float* bias,
                               const float* xres, const float* gamma, const float* beta,
                               float* out, int Kd) {
    gemm_ln_kernel<<<(NN + 63) / 64, 256, GEMMLN_SMEM_BYTES>>>(
        A, B, bias, xres, gamma, beta, out, NN, Kd);
}

extern "C" void kernel_launch(void* const* d_in, const int* in_sizes, int n_in,
                              void* d_out, int out_size) {
    const float* expr    = (const float*)d_in[0];
    const float* spatial = (const float*)d_in[1];
    const float* ipw     = (const float*)d_in[2];
    const float* ipb     = (const float*)d_in[3];
    const float* opw     = (const float*)d_in[4];
    const float* opb     = (const float*)d_in[5];
    const float* w1      = (const float*)d_in[6];
    const float* b1      = (const float*)d_in[7];
    const float* w2      = (const float*)d_in[8];
    const float* b2      = (const float*)d_in[9];
    const float* ln1g    = (const float*)d_in[10];
    const float* ln1b    = (const float*)d_in[11];
    const float* ln2g    = (const float*)d_in[12];
    const float* ln2b    = (const float*)d_in[13];
    const int*   ei      = (const int*)d_in[14];
    float* out = (float*)d_out;

    static int smem_set = 0;
    if (!smem_set) {
        cudaFuncSetAttribute(gemm_tf32_kernel,
                             cudaFuncAttributeMaxDynamicSharedMemorySize,
                             GEMM_SMEM_BYTES);
        cudaFuncSetAttribute(gemm3_kernel,
                             cudaFuncAttributeMaxDynamicSharedMemorySize,
                             GEMM_SMEM_BYTES);
        cudaFuncSetAttribute(gemm_ln_kernel,
                             cudaFuncAttributeMaxDynamicSharedMemorySize,
                             GEMMLN_SMEM_BYTES);
        smem_set = 1;
    }

    float *kv, *q, *x, *ao, *h;
    cudaGetSymbolAddress((void**)&kv, g_kv);
    cudaGetSymbolAddress((void**)&q,  g_q);
    cudaGetSymbolAddress((void**)&x,  g_x);
    cudaGetSymbolAddress((void**)&ao, g_ao);
    cudaGetSymbolAddress((void**)&h,  g_h);

    nbr_init_kernel<<<(NN + 255) / 256, 256>>>();
    nbr_scatter_kernel<<<(EE + 255) / 256, 256>>>(ei);
    nbr_fin_kernel<<<(NN + 255) / 256, 256>>>();

    const int nty = (NN + 127) / 128;     // 157 row-tiles

    // one fused launch: Q0 (expr @ Wq0), KV0 (spatial @ Wkv0), KV1 (spatial @ Wkv1)
    {
        Seg s0, s1, s2;
        s0.A = expr;    s0.B = ipw;                       s0.bias = ipb;
        s0.C = q;       s0.ntx = 2;  s0.tile_end = nty * 2;
        s1.A = spatial; s1.B = ipw + (size_t)DD * DD;     s1.bias = ipb + DD;
        s1.C = kv;      s1.ntx = 4;  s1.tile_end = s0.tile_end + nty * 4;
        s2.A = spatial; s2.B = ipw + (size_t)(3 * DD + DD) * DD; s2.bias = ipb + 3 * DD + DD;
        s2.C = kv + (size_t)NN * 2 * DD; s2.ntx = 4; s2.tile_end = s1.tile_end + nty * 4;
        gemm3_kernel<<<s2.tile_end, 256, GEMM_SMEM_BYTES>>>(s0, s1, s2);
    }

    for (int l = 0; l < LL; l++) {
        const float* xin = (l == 0) ? expr : x;

        if (l > 0) {
            const float* Wq = ipw + (size_t)l * 3 * DD * DD;
            const float* bq = ipb + (size_t)l * 3 * DD;
            run_gemm(xin, Wq, bq, q, NN, DD, DD, 0);
        }

        attn_kernel<<<(NN + 1) / 2, 256>>>(q, kv + (size_t)l * NN * 2 * DD, ao);

        run_gemm_ln(ao, opw + (size_t)l * DD * DD, opb + (size_t)l * DD,
                    xin, ln1g + (size_t)l * DD, ln1b + (size_t)l * DD, x, DD);

        run_gemm(x, w1 + (size_t)l * 2 * DD * DD, b1 + (size_t)l * 2 * DD,
                 h, NN, 2 * DD, DD, 1);

        float* xo = (l == LL - 1) ? out : x;
        run_gemm_ln(h, w2 + (size_t)l * DD * 2 * DD, b2 + (size_t)l * DD,
                    x, ln2g + (size_t)l * DD, ln2b + (size_t)l * DD, xo, 2 * DD);
    }
}